// round 14
// baseline (speedup 1.0000x reference)
#include <cuda_runtime.h>
#include <cuda_bf16.h>
#include <cstdint>

#define NPTS 400000
#define CCH  32
#define SX   480
#define SY   360
#define SZ   32
#define BB   2
#define LOOKUP_SIZE (BB*SX*SY*SZ)
#define EPSV 1e-5f

// ---- static scratch (no allocations allowed) ----
__device__ int   d_lookup[LOOKUP_SIZE];          // cell -> idx+1, 0 = empty (persistent)
__device__ __align__(16) float d_sums[64];       // [0:32) sum, [32:64) sumsq
__device__ int   d_cnt[8];                       // per-k pair counts (k != 4)
__device__ int2  d_pairs[8][NPTS];               // (out_pt, in_pt) per k
__device__ unsigned char d_flag[NPTS];           // point has >=1 valid neighbor

// ---- packed fp32x2 helpers (neighbor kernel) ----
#define FMA2(d, a, b, c) \
    asm("fma.rn.f32x2 %0, %1, %2, %3;" : "=l"(d) : "l"(a), "l"(b), "l"(c))
#define PACK2(d, x) \
    asm("mov.b64 %0, {%1, %1};" : "=l"(d) : "r"(__float_as_uint(x)))
#define UNPACK2(lo, hi, a) \
    asm("mov.b64 {%0, %1}, %2;" : "=r"(lo), "=r"(hi) : "l"(a))

__device__ __forceinline__ uint32_t smem_u32(const void* p) {
    uint32_t a;
    asm("{ .reg .u64 t; cvta.to.shared.u64 t, %1; cvt.u32.u64 %0, t; }"
        : "=r"(a) : "l"(p));
    return a;
}

#define LDSM_X4(r0, r1, r2, r3, addr) \
    asm volatile("ldmatrix.sync.aligned.m8n8.x4.shared.b16 {%0,%1,%2,%3}, [%4];" \
                 : "=r"(r0), "=r"(r1), "=r"(r2), "=r"(r3) : "r"(addr))

#define MMA_BF16(c, a0, a1, a2, a3, b0, b1) \
    asm volatile("mma.sync.aligned.m16n8k16.row.col.f32.bf16.bf16.f32 " \
                 "{%0,%1,%2,%3}, {%4,%5,%6,%7}, {%8,%9}, {%0,%1,%2,%3};" \
                 : "+f"(c[0]), "+f"(c[1]), "+f"(c[2]), "+f"(c[3]) \
                 : "r"(a0), "r"(a1), "r"(a2), "r"(a3), "r"(b0), "r"(b1))

// ============================================================
// GEMV core from global feat row (used by neighbor kernel)
// ============================================================
__device__ __forceinline__ void gemv_accum(
    const float* __restrict__ frow,
    const unsigned long long* __restrict__ wbase,
    unsigned long long acc[16])
{
    const float4* fr = (const float4*)frow;
    float4 f0 = __ldg(fr + 0), f1 = __ldg(fr + 1);
    float4 f2 = __ldg(fr + 2), f3 = __ldg(fr + 3);
    float4 f4 = __ldg(fr + 4), f5 = __ldg(fr + 5);
    float4 f6 = __ldg(fr + 6), f7 = __ldg(fr + 7);
    float fv[32] = {
        f0.x, f0.y, f0.z, f0.w, f1.x, f1.y, f1.z, f1.w,
        f2.x, f2.y, f2.z, f2.w, f3.x, f3.y, f3.z, f3.w,
        f4.x, f4.y, f4.z, f4.w, f5.x, f5.y, f5.z, f5.w,
        f6.x, f6.y, f6.z, f6.w, f7.x, f7.y, f7.z, f7.w };
#pragma unroll
    for (int cin = 0; cin < 32; cin++) {
        unsigned long long bc;
        PACK2(bc, fv[cin]);
        const ulonglong2* wv = (const ulonglong2*)(wbase + cin * 16);
#pragma unroll
        for (int h = 0; h < 8; h++) {
            ulonglong2 wp = wv[h];
            FMA2(acc[2 * h],     bc, wp.x, acc[2 * h]);
            FMA2(acc[2 * h + 1], bc, wp.y, acc[2 * h + 1]);
        }
    }
}

// ============================================================
// 1. prep: reset counters + BN sums, scatter lookup
// ============================================================
__global__ void prep_kernel(const int4* __restrict__ coords) {
    int i = blockIdx.x * blockDim.x + threadIdx.x;
    if (i < 8) d_cnt[i] = 0;
    if (i >= 8 && i < 72) d_sums[i - 8] = 0.0f;
    if (i < NPTS) {
        int4 c = coords[i];
        d_lookup[((c.x * SX + c.y) * SY + c.z) * SZ + c.w] = i + 1;
    }
}

// ============================================================
// 2. probe: per-k pair lists + flags + zero flagged out rows
// ============================================================
__global__ __launch_bounds__(256) void probe_kernel(const int4* __restrict__ coords,
                                                    float* __restrict__ out) {
    __shared__ int s_wcnt[8][8];
    __shared__ int s_wbase[8][8];
    int tid  = threadIdx.x;
    int lane = tid & 31;
    int warp = tid >> 5;
    int pt = blockIdx.x * 256 + tid;
    bool act = pt < NPTS;

    int4 cc = act ? coords[pt] : make_int4(0, 1, 0, 1);
    int base = ((cc.x * SX + cc.y) * SY + cc.z) * SZ + cc.w;

    unsigned mask = 0;
    int nb[8];
#pragma unroll
    for (int k = 0; k < 9; k++) {
        if (k == 4) continue;
        int d0 = k / 3 - 1, d2 = k % 3 - 1;
        int n0 = cc.y + d0, n2 = cc.w + d2;
        bool valid = act && (n0 >= 0) && (n0 < SX) && (n2 >= 0) && (n2 < SZ);
        int idx = valid ? (base + d0 * (SY * SZ) + d2) : 0;
        int j = valid ? __ldg(&d_lookup[idx]) : 0;
        int ki = (k < 4) ? k : k - 1;
        nb[ki] = j - 1;
        if (j > 0) mask |= (1u << ki);
    }

    if (act) d_flag[pt] = (unsigned char)(mask ? 1 : 0);

    // cooperative zero of flagged rows (these receive red.adds)
    {
        unsigned fb = __ballot_sync(0xffffffffu, act && mask);
        int wbase_pt = blockIdx.x * 256 + warp * 32;
        while (fb) {
            int p = __ffs(fb) - 1;
            fb &= fb - 1;
            out[(long long)(wbase_pt + p) * CCH + lane] = 0.0f;
        }
    }

    unsigned bal[8];
#pragma unroll
    for (int ki = 0; ki < 8; ki++)
        bal[ki] = __ballot_sync(0xffffffffu, (mask >> ki) & 1u);
    if (lane == 0) {
#pragma unroll
        for (int ki = 0; ki < 8; ki++)
            s_wcnt[ki][warp] = __popc(bal[ki]);
    }
    __syncthreads();
    if (tid < 8) {
        int run = 0;
#pragma unroll
        for (int w = 0; w < 8; w++) {
            int c = s_wcnt[tid][w];
            s_wbase[tid][w] = run;
            run += c;
        }
        int g = atomicAdd(&d_cnt[tid], run);
#pragma unroll
        for (int w = 0; w < 8; w++)
            s_wbase[tid][w] += g;
    }
    __syncthreads();
#pragma unroll
    for (int ki = 0; ki < 8; ki++) {
        if ((mask >> ki) & 1u) {
            int rank = __popc(bal[ki] & ((1u << lane) - 1u));
            d_pairs[ki][s_wbase[ki][warp] + rank] = make_int2(pt, nb[ki]);
        }
    }
}

// ============================================================
// 3. neighbor conv: grid.y = ki, one thread per pair, uniform-k
// ============================================================
__global__ __launch_bounds__(256) void neighbor_kernel(
    const float* __restrict__ feat,
    const float* __restrict__ weight,
    float*       __restrict__ out)
{
    int ki = blockIdx.y;
    int k  = (ki < 4) ? ki : ki + 1;
    __shared__ unsigned long long w2[512];
    {
        const unsigned long long* ws =
            (const unsigned long long*)(weight + k * 1024);
        for (int i = threadIdx.x; i < 512; i += 256)
            w2[i] = ws[i];
    }
    __syncthreads();

    int n = d_cnt[ki];
    for (int p = blockIdx.x * 256 + threadIdx.x; p < n; p += gridDim.x * 256) {
        int2 pr = d_pairs[ki][p];
        unsigned long long acc[16];
#pragma unroll
        for (int q = 0; q < 16; q++) acc[q] = 0ull;
        gemv_accum(feat + (long long)pr.y * CCH, w2, acc);

        float* orow = out + (long long)pr.x * CCH;
#pragma unroll
        for (int h = 0; h < 8; h++) {
            unsigned int u0, u1, u2, u3;
            UNPACK2(u0, u1, acc[2 * h]);
            UNPACK2(u2, u3, acc[2 * h + 1]);
            asm volatile("red.global.add.v4.f32 [%0], {%1, %2, %3, %4};"
                         :: "l"(orow + 4 * h),
                            "f"(__uint_as_float(u0)), "f"(__uint_as_float(u1)),
                            "f"(__uint_as_float(u2)), "f"(__uint_as_float(u3))
                         : "memory");
        }
    }
}

// ============================================================
// 4. self conv via mma.sync bf16 3-product split (M=256, N=32)
//    512 threads, 16 warps x 1 tile; partial rows prefetched into
//    registers so their latency hides behind the MMA phase
// ============================================================
#define ASTR 72       // bf16/row: 144 B = 9 x 16B (odd) -> ldmatrix conflict-free
#define BSTR 104      // bf16/row: 208 B = 13 x 16B (odd)
#define BPTS 256

__global__ __launch_bounds__(512) void selfleaky_mma_kernel(
    const float* __restrict__ feat,
    const float* __restrict__ weight,
    float*       __restrict__ out)
{
    __shared__ __align__(16) __nv_bfloat16 s_A[BPTS * ASTR];  // 36864 B
    __shared__ __align__(16) __nv_bfloat16 s_B[32 * BSTR];    //  6656 B
    __shared__ unsigned char s_flag[BPTS];
    __shared__ float s_sum[32], s_sq[32];
    float* s_out = (float*)s_A;   // overlay: 256*36*4 = 36864 B exact

    int tid  = threadIdx.x;
    int wrp  = tid >> 5;
    int lane = tid & 31;
    int blk0 = blockIdx.x * BPTS;
    int gbase = blk0 * 8;                 // float4 index base
    const int gmax = NPTS * 8;

    if (tid < 32) { s_sum[tid] = 0.0f; s_sq[tid] = 0.0f; }
    if (tid < BPTS) s_flag[tid] = (blk0 + tid < NPTS) ? d_flag[blk0 + tid] : 0;

    // ---- stage A: coalesced LDG.128, bf16 split, 2 regions, STS.64 ----
    {
        const float4* f4 = (const float4*)feat;
#pragma unroll
        for (int i = 0; i < 4; i++) {
            int idx = i * 512 + tid;               // 0..2047
            int g = gbase + idx;
            float4 v = (g < gmax) ? __ldg(f4 + g)
                                  : make_float4(0.f, 0.f, 0.f, 0.f);
            int r  = idx >> 3;
            int c4 = (idx & 7) << 2;               // bf16 col: 0,4,..28
            __nv_bfloat162 h01 = __floats2bfloat162_rn(v.x, v.y);
            __nv_bfloat162 h23 = __floats2bfloat162_rn(v.z, v.w);
            __nv_bfloat162 l01 = __floats2bfloat162_rn(
                v.x - __bfloat162float(h01.x), v.y - __bfloat162float(h01.y));
            __nv_bfloat162 l23 = __floats2bfloat162_rn(
                v.z - __bfloat162float(h23.x), v.w - __bfloat162float(h23.y));
            uint2 hh = make_uint2(*(uint32_t*)&h01, *(uint32_t*)&h23);
            uint2 ll = make_uint2(*(uint32_t*)&l01, *(uint32_t*)&l23);
            *(uint2*)&s_A[r * ASTR + c4]      = hh;   // xh cols 0..31
            *(uint2*)&s_A[r * ASTR + 32 + c4] = ll;   // xl cols 32..63
        }
    }

    // ---- stage B: weights k=4, transpose to [cout][wh|wh|wl] ----
    if (tid < 256) {
        float4 wv = __ldg((const float4*)(weight + 4 * 1024) + tid);
        int el  = tid * 4;
        int cin = el >> 5;
        int n0  = el & 31;
        float wf[4] = { wv.x, wv.y, wv.z, wv.w };
#pragma unroll
        for (int j = 0; j < 4; j++) {
            int n = n0 + j;
            __nv_bfloat16 wh = __float2bfloat16(wf[j]);
            __nv_bfloat16 wl = __float2bfloat16(wf[j] - __bfloat162float(wh));
            s_B[n * BSTR + cin]      = wh;
            s_B[n * BSTR + 32 + cin] = wh;
            s_B[n * BSTR + 64 + cin] = wl;
        }
    }
    __syncthreads();

    // ---- prefetch neighbor partials (latency hides behind MMA phase) ----
    float4 part[4];
    {
        const float4* o4 = (const float4*)out;
#pragma unroll
        for (int i = 0; i < 4; i++) {
            int idx = i * 512 + tid;
            int g = gbase + idx;
            int r = idx >> 3;
            part[i] = (g < gmax && s_flag[r]) ? __ldg(o4 + g)
                                              : make_float4(0.f, 0.f, 0.f, 0.f);
        }
    }

    // ---- warp MMA: warp wrp owns rows [16*wrp, 16*wrp+16) ----
    float c0[4] = {0,0,0,0}, c1[4] = {0,0,0,0},
          c2[4] = {0,0,0,0}, c3[4] = {0,0,0,0};
    {
        uint32_t a_base = smem_u32(s_A) + ((wrp * 16 + (lane & 15)) * ASTR
                        + (lane >> 4) * 8) * 2;
        uint32_t b_base0 = smem_u32(s_B) + ((lane & 15) * BSTR
                         + (lane >> 4) * 8) * 2;
        uint32_t b_base1 = b_base0 + 16 * BSTR * 2;
#pragma unroll
        for (int s = 0; s < 6; s++) {
            uint32_t a_koff = (s < 4 ? s : s - 4) * 32;   // bytes (16 bf16)
            uint32_t b_koff = s * 32;
            uint32_t a0, a1, a2, a3, p0, p1, p2, p3, q0, q1, q2, q3;
            LDSM_X4(a0, a1, a2, a3, a_base + a_koff);
            LDSM_X4(p0, p1, p2, p3, b_base0 + b_koff);
            LDSM_X4(q0, q1, q2, q3, b_base1 + b_koff);
            MMA_BF16(c0, a0, a1, a2, a3, p0, p2);   // couts 0-7
            MMA_BF16(c1, a0, a1, a2, a3, p1, p3);   // couts 8-15
            MMA_BF16(c2, a0, a1, a2, a3, q0, q2);   // couts 16-23
            MMA_BF16(c3, a0, a1, a2, a3, q1, q3);   // couts 24-31
        }
    }

    // ---- warp-local epilogue: acc -> s_out (own rows only; no barrier) ----
    {
        int g  = lane >> 2;
        int tg = lane & 3;
        int r0 = wrp * 16 + g;
        float* ro = &s_out[r0 * 36 + 2 * tg];
        float* r8 = &s_out[(r0 + 8) * 36 + 2 * tg];
        *(float2*)(ro + 0)  = make_float2(c0[0], c0[1]);
        *(float2*)(r8 + 0)  = make_float2(c0[2], c0[3]);
        *(float2*)(ro + 8)  = make_float2(c1[0], c1[1]);
        *(float2*)(r8 + 8)  = make_float2(c1[2], c1[3]);
        *(float2*)(ro + 16) = make_float2(c2[0], c2[1]);
        *(float2*)(r8 + 16) = make_float2(c2[2], c2[3]);
        *(float2*)(ro + 24) = make_float2(c3[0], c3[1]);
        *(float2*)(r8 + 24) = make_float2(c3[2], c3[3]);
    }
    __syncthreads();

    // ---- fused writeback: +prefetched partials, leaky, store, BN ----
    float bs0 = 0.f, bs1 = 0.f, bs2 = 0.f, bs3 = 0.f;
    float bq0 = 0.f, bq1 = 0.f, bq2 = 0.f, bq3 = 0.f;
    {
        float4* o4 = (float4*)out;
#pragma unroll
        for (int i = 0; i < 4; i++) {
            int idx = i * 512 + tid;
            int g = gbase + idx;
            if (g < gmax) {
                int r = idx >> 3;
                int c = (idx & 7) << 2;
                float4 v = *(const float4*)&s_out[r * 36 + c];
                v.x += part[i].x; v.y += part[i].y;
                v.z += part[i].z; v.w += part[i].w;
                v.x = fmaxf(v.x, 0.01f * v.x);
                v.y = fmaxf(v.y, 0.01f * v.y);
                v.z = fmaxf(v.z, 0.01f * v.z);
                v.w = fmaxf(v.w, 0.01f * v.w);
                o4[g] = v;
                bs0 += v.x; bq0 = fmaf(v.x, v.x, bq0);
                bs1 += v.y; bq1 = fmaf(v.y, v.y, bq1);
                bs2 += v.z; bq2 = fmaf(v.z, v.z, bq2);
                bs3 += v.w; bq3 = fmaf(v.w, v.w, bq3);
            }
        }
    }
    {
        int cq = (tid & 7) * 4;
        atomicAdd(&s_sum[cq + 0], bs0);
        atomicAdd(&s_sum[cq + 1], bs1);
        atomicAdd(&s_sum[cq + 2], bs2);
        atomicAdd(&s_sum[cq + 3], bs3);
        atomicAdd(&s_sq[cq + 0], bq0);
        atomicAdd(&s_sq[cq + 1], bq1);
        atomicAdd(&s_sq[cq + 2], bq2);
        atomicAdd(&s_sq[cq + 3], bq3);
    }
    __syncthreads();
    if (tid < 32) {
        atomicAdd(&d_sums[tid],      s_sum[tid]);
        atomicAdd(&d_sums[32 + tid], s_sq[tid]);
    }
}

// ============================================================
// 5. normalize in place; scale/shift computed per block (fused finalize)
// ============================================================
__global__ __launch_bounds__(256) void norm_kernel(float4* __restrict__ y,
                                                   const float* __restrict__ gamma,
                                                   const float* __restrict__ beta) {
    __shared__ float s_sc[32], s_sh[32];
    if (threadIdx.x < 32) {
        int c = threadIdx.x;
        const float invN = 1.0f / (float)NPTS;
        float sum = __ldg(&d_sums[c]);
        float sq  = __ldg(&d_sums[32 + c]);
        float mean = sum * invN;
        float var  = sq * invN - mean * mean;
        float sc   = __ldg(&gamma[c]) * rsqrtf(var + EPSV);
        s_sc[c] = sc;
        s_sh[c] = __ldg(&beta[c]) - mean * sc;
    }
    __syncthreads();
    int base = blockIdx.x * 1024;
#pragma unroll
    for (int i = 0; i < 4; i++) {
        int t = base + i * 256 + threadIdx.x;    // total = 3.2M, grid exact
        int c0 = (t & 7) * 4;
        float4 v = y[t];
        v.x = fmaf(v.x, s_sc[c0 + 0], s_sh[c0 + 0]);
        v.y = fmaf(v.y, s_sc[c0 + 1], s_sh[c0 + 1]);
        v.z = fmaf(v.z, s_sc[c0 + 2], s_sh[c0 + 2]);
        v.w = fmaf(v.w, s_sc[c0 + 3], s_sh[c0 + 3]);
        y[t] = v;
    }
}

// ============================================================
extern "C" void kernel_launch(void* const* d_in, const int* in_sizes, int n_in,
                              void* d_out, int out_size) {
    const float* feat   = (const float*)d_in[0];
    const int4*  coords = (const int4*)d_in[1];
    const float* weight = (const float*)d_in[2];
    const float* gamma  = (const float*)d_in[3];
    const float* beta   = (const float*)d_in[4];
    float* out = (float*)d_out;

    prep_kernel<<<(NPTS + 255) / 256, 256>>>(coords);
    probe_kernel<<<(NPTS + 255) / 256, 256>>>(coords, out);
    neighbor_kernel<<<dim3(64, 8), 256>>>(feat, weight, out);
    selfleaky_mma_kernel<<<(NPTS + BPTS - 1) / BPTS, 512>>>(feat, weight, out);
    norm_kernel<<<NPTS * 8 / 1024, 256>>>((float4*)out, gamma, beta);
}

// round 15
// speedup vs baseline: 1.2348x; 1.2348x over previous
#include <cuda_runtime.h>
#include <cuda_bf16.h>
#include <cstdint>

#define NPTS 400000
#define CCH  32
#define SX   480
#define SY   360
#define SZ   32
#define BB   2
#define LOOKUP_SIZE (BB*SX*SY*SZ)
#define EPSV 1e-5f

// ---- static scratch (no allocations allowed) ----
__device__ int   d_lookup[LOOKUP_SIZE];          // cell -> idx+1, 0 = empty (persistent)
__device__ __align__(16) float d_sums[64];       // [0:32) sum, [32:64) sumsq
__device__ int   d_cnt[8];                       // per-k pair counts (k != 4)
__device__ int2  d_pairs[8][NPTS];               // (out_pt, in_pt) per k
__device__ unsigned char d_flag[NPTS];           // point has >=1 valid neighbor

// ---- packed fp32x2 helpers (neighbor kernel) ----
#define FMA2(d, a, b, c) \
    asm("fma.rn.f32x2 %0, %1, %2, %3;" : "=l"(d) : "l"(a), "l"(b), "l"(c))
#define PACK2(d, x) \
    asm("mov.b64 %0, {%1, %1};" : "=l"(d) : "r"(__float_as_uint(x)))
#define UNPACK2(lo, hi, a) \
    asm("mov.b64 {%0, %1}, %2;" : "=r"(lo), "=r"(hi) : "l"(a))

__device__ __forceinline__ uint32_t smem_u32(const void* p) {
    uint32_t a;
    asm("{ .reg .u64 t; cvta.to.shared.u64 t, %1; cvt.u32.u64 %0, t; }"
        : "=r"(a) : "l"(p));
    return a;
}

#define LDSM_X4(r0, r1, r2, r3, addr) \
    asm volatile("ldmatrix.sync.aligned.m8n8.x4.shared.b16 {%0,%1,%2,%3}, [%4];" \
                 : "=r"(r0), "=r"(r1), "=r"(r2), "=r"(r3) : "r"(addr))

#define MMA_BF16(c, a0, a1, a2, a3, b0, b1) \
    asm volatile("mma.sync.aligned.m16n8k16.row.col.f32.bf16.bf16.f32 " \
                 "{%0,%1,%2,%3}, {%4,%5,%6,%7}, {%8,%9}, {%0,%1,%2,%3};" \
                 : "+f"(c[0]), "+f"(c[1]), "+f"(c[2]), "+f"(c[3]) \
                 : "r"(a0), "r"(a1), "r"(a2), "r"(a3), "r"(b0), "r"(b1))

// ============================================================
// GEMV core from global feat row (used by neighbor kernel)
// ============================================================
__device__ __forceinline__ void gemv_accum(
    const float* __restrict__ frow,
    const unsigned long long* __restrict__ wbase,
    unsigned long long acc[16])
{
    const float4* fr = (const float4*)frow;
    float4 f0 = __ldg(fr + 0), f1 = __ldg(fr + 1);
    float4 f2 = __ldg(fr + 2), f3 = __ldg(fr + 3);
    float4 f4 = __ldg(fr + 4), f5 = __ldg(fr + 5);
    float4 f6 = __ldg(fr + 6), f7 = __ldg(fr + 7);
    float fv[32] = {
        f0.x, f0.y, f0.z, f0.w, f1.x, f1.y, f1.z, f1.w,
        f2.x, f2.y, f2.z, f2.w, f3.x, f3.y, f3.z, f3.w,
        f4.x, f4.y, f4.z, f4.w, f5.x, f5.y, f5.z, f5.w,
        f6.x, f6.y, f6.z, f6.w, f7.x, f7.y, f7.z, f7.w };
#pragma unroll
    for (int cin = 0; cin < 32; cin++) {
        unsigned long long bc;
        PACK2(bc, fv[cin]);
        const ulonglong2* wv = (const ulonglong2*)(wbase + cin * 16);
#pragma unroll
        for (int h = 0; h < 8; h++) {
            ulonglong2 wp = wv[h];
            FMA2(acc[2 * h],     bc, wp.x, acc[2 * h]);
            FMA2(acc[2 * h + 1], bc, wp.y, acc[2 * h + 1]);
        }
    }
}

// ============================================================
// 1. prep: reset counters + BN sums, scatter lookup
// ============================================================
__global__ void prep_kernel(const int4* __restrict__ coords) {
    int i = blockIdx.x * blockDim.x + threadIdx.x;
    if (i < 8) d_cnt[i] = 0;
    if (i >= 8 && i < 72) d_sums[i - 8] = 0.0f;
    if (i < NPTS) {
        int4 c = coords[i];
        d_lookup[((c.x * SX + c.y) * SY + c.z) * SZ + c.w] = i + 1;
    }
}

// ============================================================
// 2. probe: per-k pair lists + flags + zero flagged out rows
// ============================================================
__global__ __launch_bounds__(256) void probe_kernel(const int4* __restrict__ coords,
                                                    float* __restrict__ out) {
    __shared__ int s_wcnt[8][8];
    __shared__ int s_wbase[8][8];
    int tid  = threadIdx.x;
    int lane = tid & 31;
    int warp = tid >> 5;
    int pt = blockIdx.x * 256 + tid;
    bool act = pt < NPTS;

    int4 cc = act ? coords[pt] : make_int4(0, 1, 0, 1);
    int base = ((cc.x * SX + cc.y) * SY + cc.z) * SZ + cc.w;

    unsigned mask = 0;
    int nb[8];
#pragma unroll
    for (int k = 0; k < 9; k++) {
        if (k == 4) continue;
        int d0 = k / 3 - 1, d2 = k % 3 - 1;
        int n0 = cc.y + d0, n2 = cc.w + d2;
        bool valid = act && (n0 >= 0) && (n0 < SX) && (n2 >= 0) && (n2 < SZ);
        int idx = valid ? (base + d0 * (SY * SZ) + d2) : 0;
        int j = valid ? __ldg(&d_lookup[idx]) : 0;
        int ki = (k < 4) ? k : k - 1;
        nb[ki] = j - 1;
        if (j > 0) mask |= (1u << ki);
    }

    if (act) d_flag[pt] = (unsigned char)(mask ? 1 : 0);

    // cooperative zero of flagged rows (these receive red.adds)
    {
        unsigned fb = __ballot_sync(0xffffffffu, act && mask);
        int wbase_pt = blockIdx.x * 256 + warp * 32;
        while (fb) {
            int p = __ffs(fb) - 1;
            fb &= fb - 1;
            out[(long long)(wbase_pt + p) * CCH + lane] = 0.0f;
        }
    }

    unsigned bal[8];
#pragma unroll
    for (int ki = 0; ki < 8; ki++)
        bal[ki] = __ballot_sync(0xffffffffu, (mask >> ki) & 1u);
    if (lane == 0) {
#pragma unroll
        for (int ki = 0; ki < 8; ki++)
            s_wcnt[ki][warp] = __popc(bal[ki]);
    }
    __syncthreads();
    if (tid < 8) {
        int run = 0;
#pragma unroll
        for (int w = 0; w < 8; w++) {
            int c = s_wcnt[tid][w];
            s_wbase[tid][w] = run;
            run += c;
        }
        int g = atomicAdd(&d_cnt[tid], run);
#pragma unroll
        for (int w = 0; w < 8; w++)
            s_wbase[tid][w] += g;
    }
    __syncthreads();
#pragma unroll
    for (int ki = 0; ki < 8; ki++) {
        if ((mask >> ki) & 1u) {
            int rank = __popc(bal[ki] & ((1u << lane) - 1u));
            d_pairs[ki][s_wbase[ki][warp] + rank] = make_int2(pt, nb[ki]);
        }
    }
}

// ============================================================
// 3. neighbor conv: grid.y = ki, one thread per pair, uniform-k
// ============================================================
__global__ __launch_bounds__(256) void neighbor_kernel(
    const float* __restrict__ feat,
    const float* __restrict__ weight,
    float*       __restrict__ out)
{
    int ki = blockIdx.y;
    int k  = (ki < 4) ? ki : ki + 1;
    __shared__ unsigned long long w2[512];
    {
        const unsigned long long* ws =
            (const unsigned long long*)(weight + k * 1024);
        for (int i = threadIdx.x; i < 512; i += 256)
            w2[i] = ws[i];
    }
    __syncthreads();

    int n = d_cnt[ki];
    for (int p = blockIdx.x * 256 + threadIdx.x; p < n; p += gridDim.x * 256) {
        int2 pr = d_pairs[ki][p];
        unsigned long long acc[16];
#pragma unroll
        for (int q = 0; q < 16; q++) acc[q] = 0ull;
        gemv_accum(feat + (long long)pr.y * CCH, w2, acc);

        float* orow = out + (long long)pr.x * CCH;
#pragma unroll
        for (int h = 0; h < 8; h++) {
            unsigned int u0, u1, u2, u3;
            UNPACK2(u0, u1, acc[2 * h]);
            UNPACK2(u2, u3, acc[2 * h + 1]);
            asm volatile("red.global.add.v4.f32 [%0], {%1, %2, %3, %4};"
                         :: "l"(orow + 4 * h),
                            "f"(__uint_as_float(u0)), "f"(__uint_as_float(u1)),
                            "f"(__uint_as_float(u2)), "f"(__uint_as_float(u3))
                         : "memory");
        }
    }
}

// ============================================================
// 4. self conv via mma.sync bf16 3-product split (M=256, N=32)
//    2 M-tiles per warp sharing B fragments; warp-local epilogue
//    (R13 structure; launch_bounds(256,4) -> 4 CTAs/SM)
// ============================================================
#define ASTR 72       // bf16/row: 144 B = 9 x 16B (odd) -> ldmatrix conflict-free
#define BSTR 104      // bf16/row: 208 B = 13 x 16B (odd)
#define BPTS 256

__global__ __launch_bounds__(256, 4) void selfleaky_mma_kernel(
    const float* __restrict__ feat,
    const float* __restrict__ weight,
    float*       __restrict__ out)
{
    __shared__ __align__(16) __nv_bfloat16 s_A[BPTS * ASTR];  // 36864 B
    __shared__ __align__(16) __nv_bfloat16 s_B[32 * BSTR];    //  6656 B
    __shared__ unsigned char s_flag[BPTS];
    __shared__ float s_sum[32], s_sq[32];
    float* s_out = (float*)s_A;   // overlay: 256*36*4 = 36864 B exact

    int tid  = threadIdx.x;
    int wrp  = tid >> 5;
    int lane = tid & 31;
    int blk0 = blockIdx.x * BPTS;
    int gbase = blk0 * 8;                 // float4 index base
    const int gmax = NPTS * 8;

    if (tid < 32) { s_sum[tid] = 0.0f; s_sq[tid] = 0.0f; }
    s_flag[tid] = (blk0 + tid < NPTS) ? d_flag[blk0 + tid] : 0;

    // ---- stage A: coalesced LDG.128, bf16 split, 2 regions, STS.64 ----
    {
        const float4* f4 = (const float4*)feat;
#pragma unroll
        for (int i = 0; i < 8; i++) {
            int idx = i * 256 + tid;               // 0..2047
            int g = gbase + idx;
            float4 v = (g < gmax) ? __ldg(f4 + g)
                                  : make_float4(0.f, 0.f, 0.f, 0.f);
            int r  = idx >> 3;
            int c4 = (idx & 7) << 2;               // bf16 col: 0,4,..28
            __nv_bfloat162 h01 = __floats2bfloat162_rn(v.x, v.y);
            __nv_bfloat162 h23 = __floats2bfloat162_rn(v.z, v.w);
            __nv_bfloat162 l01 = __floats2bfloat162_rn(
                v.x - __bfloat162float(h01.x), v.y - __bfloat162float(h01.y));
            __nv_bfloat162 l23 = __floats2bfloat162_rn(
                v.z - __bfloat162float(h23.x), v.w - __bfloat162float(h23.y));
            uint2 hh = make_uint2(*(uint32_t*)&h01, *(uint32_t*)&h23);
            uint2 ll = make_uint2(*(uint32_t*)&l01, *(uint32_t*)&l23);
            *(uint2*)&s_A[r * ASTR + c4]      = hh;   // xh cols 0..31
            *(uint2*)&s_A[r * ASTR + 32 + c4] = ll;   // xl cols 32..63
        }
    }

    // ---- stage B: weights k=4, transpose to [cout][wh|wh|wl] ----
    {
        float4 wv = __ldg((const float4*)(weight + 4 * 1024) + tid);
        int el  = tid * 4;
        int cin = el >> 5;
        int n0  = el & 31;
        float wf[4] = { wv.x, wv.y, wv.z, wv.w };
#pragma unroll
        for (int j = 0; j < 4; j++) {
            int n = n0 + j;
            __nv_bfloat16 wh = __float2bfloat16(wf[j]);
            __nv_bfloat16 wl = __float2bfloat16(wf[j] - __bfloat162float(wh));
            s_B[n * BSTR + cin]      = wh;
            s_B[n * BSTR + 32 + cin] = wh;
            s_B[n * BSTR + 64 + cin] = wl;
        }
    }
    __syncthreads();

    // ---- warp MMA: 2 tiles, rows [16w,16w+16) and +128; shared B frags ----
    float c00[4] = {0,0,0,0}, c01[4] = {0,0,0,0},
          c02[4] = {0,0,0,0}, c03[4] = {0,0,0,0};
    float c10[4] = {0,0,0,0}, c11[4] = {0,0,0,0},
          c12[4] = {0,0,0,0}, c13[4] = {0,0,0,0};
    {
        uint32_t a_base0 = smem_u32(s_A) + ((wrp * 16 + (lane & 15)) * ASTR
                         + (lane >> 4) * 8) * 2;
        uint32_t a_base1 = a_base0 + 128 * ASTR * 2;
        uint32_t b_base0 = smem_u32(s_B) + ((lane & 15) * BSTR
                         + (lane >> 4) * 8) * 2;
        uint32_t b_base1 = b_base0 + 16 * BSTR * 2;
#pragma unroll
        for (int s = 0; s < 6; s++) {
            uint32_t a_koff = (s < 4 ? s : s - 4) * 32;   // bytes (16 bf16)
            uint32_t b_koff = s * 32;
            uint32_t p0, p1, p2, p3, q0, q1, q2, q3;
            LDSM_X4(p0, p1, p2, p3, b_base0 + b_koff);
            LDSM_X4(q0, q1, q2, q3, b_base1 + b_koff);
            uint32_t a0, a1, a2, a3;
            LDSM_X4(a0, a1, a2, a3, a_base0 + a_koff);
            MMA_BF16(c00, a0, a1, a2, a3, p0, p2);
            MMA_BF16(c01, a0, a1, a2, a3, p1, p3);
            MMA_BF16(c02, a0, a1, a2, a3, q0, q2);
            MMA_BF16(c03, a0, a1, a2, a3, q1, q3);
            uint32_t e0, e1, e2, e3;
            LDSM_X4(e0, e1, e2, e3, a_base1 + a_koff);
            MMA_BF16(c10, e0, e1, e2, e3, p0, p2);
            MMA_BF16(c11, e0, e1, e2, e3, p1, p3);
            MMA_BF16(c12, e0, e1, e2, e3, q0, q2);
            MMA_BF16(c13, e0, e1, e2, e3, q1, q3);
        }
    }

    // ---- warp-local epilogue: acc -> s_out (own rows only; no barrier) ----
    {
        int g  = lane >> 2;
        int tg = lane & 3;
        int r0 = wrp * 16 + g;
        float* ro = &s_out[r0 * 36 + 2 * tg];
        float* r8 = &s_out[(r0 + 8) * 36 + 2 * tg];
        *(float2*)(ro + 0)  = make_float2(c00[0], c00[1]);
        *(float2*)(r8 + 0)  = make_float2(c00[2], c00[3]);
        *(float2*)(ro + 8)  = make_float2(c01[0], c01[1]);
        *(float2*)(r8 + 8)  = make_float2(c01[2], c01[3]);
        *(float2*)(ro + 16) = make_float2(c02[0], c02[1]);
        *(float2*)(r8 + 16) = make_float2(c02[2], c02[3]);
        *(float2*)(ro + 24) = make_float2(c03[0], c03[1]);
        *(float2*)(r8 + 24) = make_float2(c03[2], c03[3]);
        float* so = ro + 128 * 36;
        float* s8 = r8 + 128 * 36;
        *(float2*)(so + 0)  = make_float2(c10[0], c10[1]);
        *(float2*)(s8 + 0)  = make_float2(c10[2], c10[3]);
        *(float2*)(so + 8)  = make_float2(c11[0], c11[1]);
        *(float2*)(s8 + 8)  = make_float2(c11[2], c11[3]);
        *(float2*)(so + 16) = make_float2(c12[0], c12[1]);
        *(float2*)(s8 + 16) = make_float2(c12[2], c12[3]);
        *(float2*)(so + 24) = make_float2(c13[0], c13[1]);
        *(float2*)(s8 + 24) = make_float2(c13[2], c13[3]);
    }
    __syncthreads();

    // ---- fused writeback: +partials, leaky, store, BN accumulate ----
    float bs0 = 0.f, bs1 = 0.f, bs2 = 0.f, bs3 = 0.f;
    float bq0 = 0.f, bq1 = 0.f, bq2 = 0.f, bq3 = 0.f;
    {
        float4* o4 = (float4*)out;
#pragma unroll
        for (int i = 0; i < 8; i++) {
            int idx = i * 256 + tid;
            int g = gbase + idx;
            if (g < gmax) {
                int r = idx >> 3;
                int c = (idx & 7) << 2;
                float4 v = *(const float4*)&s_out[r * 36 + c];
                if (s_flag[r]) {
                    float4 p = __ldg(o4 + g);
                    v.x += p.x; v.y += p.y; v.z += p.z; v.w += p.w;
                }
                v.x = fmaxf(v.x, 0.01f * v.x);
                v.y = fmaxf(v.y, 0.01f * v.y);
                v.z = fmaxf(v.z, 0.01f * v.z);
                v.w = fmaxf(v.w, 0.01f * v.w);
                o4[g] = v;
                bs0 += v.x; bq0 = fmaf(v.x, v.x, bq0);
                bs1 += v.y; bq1 = fmaf(v.y, v.y, bq1);
                bs2 += v.z; bq2 = fmaf(v.z, v.z, bq2);
                bs3 += v.w; bq3 = fmaf(v.w, v.w, bq3);
            }
        }
    }
    {
        int cq = (tid & 7) * 4;
        atomicAdd(&s_sum[cq + 0], bs0);
        atomicAdd(&s_sum[cq + 1], bs1);
        atomicAdd(&s_sum[cq + 2], bs2);
        atomicAdd(&s_sum[cq + 3], bs3);
        atomicAdd(&s_sq[cq + 0], bq0);
        atomicAdd(&s_sq[cq + 1], bq1);
        atomicAdd(&s_sq[cq + 2], bq2);
        atomicAdd(&s_sq[cq + 3], bq3);
    }
    __syncthreads();
    if (tid < 32) {
        atomicAdd(&d_sums[tid],      s_sum[tid]);
        atomicAdd(&d_sums[32 + tid], s_sq[tid]);
    }
}

// ============================================================
// 5. normalize in place; scale/shift computed per block (fused finalize)
// ============================================================
__global__ __launch_bounds__(256) void norm_kernel(float4* __restrict__ y,
                                                   const float* __restrict__ gamma,
                                                   const float* __restrict__ beta) {
    __shared__ float s_sc[32], s_sh[32];
    if (threadIdx.x < 32) {
        int c = threadIdx.x;
        const float invN = 1.0f / (float)NPTS;
        float sum = __ldg(&d_sums[c]);
        float sq  = __ldg(&d_sums[32 + c]);
        float mean = sum * invN;
        float var  = sq * invN - mean * mean;
        float sc   = __ldg(&gamma[c]) * rsqrtf(var + EPSV);
        s_sc[c] = sc;
        s_sh[c] = __ldg(&beta[c]) - mean * sc;
    }
    __syncthreads();
    int base = blockIdx.x * 1024;
#pragma unroll
    for (int i = 0; i < 4; i++) {
        int t = base + i * 256 + threadIdx.x;    // total = 3.2M, grid exact
        int c0 = (t & 7) * 4;
        float4 v = y[t];
        v.x = fmaf(v.x, s_sc[c0 + 0], s_sh[c0 + 0]);
        v.y = fmaf(v.y, s_sc[c0 + 1], s_sh[c0 + 1]);
        v.z = fmaf(v.z, s_sc[c0 + 2], s_sh[c0 + 2]);
        v.w = fmaf(v.w, s_sc[c0 + 3], s_sh[c0 + 3]);
        y[t] = v;
    }
}

// ============================================================
extern "C" void kernel_launch(void* const* d_in, const int* in_sizes, int n_in,
                              void* d_out, int out_size) {
    const float* feat   = (const float*)d_in[0];
    const int4*  coords = (const int4*)d_in[1];
    const float* weight = (const float*)d_in[2];
    const float* gamma  = (const float*)d_in[3];
    const float* beta   = (const float*)d_in[4];
    float* out = (float*)d_out;

    prep_kernel<<<(NPTS + 255) / 256, 256>>>(coords);
    probe_kernel<<<(NPTS + 255) / 256, 256>>>(coords, out);
    neighbor_kernel<<<dim3(64, 8), 256>>>(feat, weight, out);
    selfleaky_mma_kernel<<<(NPTS + BPTS - 1) / BPTS, 256>>>(feat, weight, out);
    norm_kernel<<<NPTS * 8 / 1024, 256>>>((float4*)out, gamma, beta);
}

// round 16
// speedup vs baseline: 1.2616x; 1.0218x over previous
#include <cuda_runtime.h>
#include <cuda_bf16.h>
#include <cstdint>

#define NPTS 400000
#define CCH  32
#define SX   480
#define SY   360
#define SZ   32
#define BB   2
#define LOOKUP_SIZE (BB*SX*SY*SZ)
#define EPSV 1e-5f

// ---- static scratch (no allocations allowed) ----
__device__ int   d_lookup[LOOKUP_SIZE];          // cell -> idx+1, 0 = empty (persistent)
__device__ __align__(16) float d_sums[64];       // [0:32) sum, [32:64) sumsq
__device__ int   d_cnt[8];                       // per-k pair counts (k != 4)
__device__ int2  d_pairs[8][NPTS];               // (out_pt, in_pt) per k
__device__ unsigned char d_flag[NPTS];           // point has >=1 valid neighbor

// ---- packed fp32x2 helpers (neighbor kernel) ----
#define FMA2(d, a, b, c) \
    asm("fma.rn.f32x2 %0, %1, %2, %3;" : "=l"(d) : "l"(a), "l"(b), "l"(c))
#define PACK2(d, x) \
    asm("mov.b64 %0, {%1, %1};" : "=l"(d) : "r"(__float_as_uint(x)))
#define UNPACK2(lo, hi, a) \
    asm("mov.b64 {%0, %1}, %2;" : "=r"(lo), "=r"(hi) : "l"(a))

__device__ __forceinline__ uint32_t smem_u32(const void* p) {
    uint32_t a;
    asm("{ .reg .u64 t; cvta.to.shared.u64 t, %1; cvt.u32.u64 %0, t; }"
        : "=r"(a) : "l"(p));
    return a;
}

__device__ __forceinline__ float4 ldcs4(const float4* p) {
    float4 v;
    asm volatile("ld.global.cs.v4.f32 {%0,%1,%2,%3}, [%4];"
                 : "=f"(v.x), "=f"(v.y), "=f"(v.z), "=f"(v.w) : "l"(p));
    return v;
}

#define LDSM_X4(r0, r1, r2, r3, addr) \
    asm volatile("ldmatrix.sync.aligned.m8n8.x4.shared.b16 {%0,%1,%2,%3}, [%4];" \
                 : "=r"(r0), "=r"(r1), "=r"(r2), "=r"(r3) : "r"(addr))

#define MMA_BF16(c, a0, a1, a2, a3, b0, b1) \
    asm volatile("mma.sync.aligned.m16n8k16.row.col.f32.bf16.bf16.f32 " \
                 "{%0,%1,%2,%3}, {%4,%5,%6,%7}, {%8,%9}, {%0,%1,%2,%3};" \
                 : "+f"(c[0]), "+f"(c[1]), "+f"(c[2]), "+f"(c[3]) \
                 : "r"(a0), "r"(a1), "r"(a2), "r"(a3), "r"(b0), "r"(b1))

// ============================================================
// GEMV core from global feat row (used by neighbor kernel)
// ============================================================
__device__ __forceinline__ void gemv_accum(
    const float* __restrict__ frow,
    const unsigned long long* __restrict__ wbase,
    unsigned long long acc[16])
{
    const float4* fr = (const float4*)frow;
    float4 f0 = __ldg(fr + 0), f1 = __ldg(fr + 1);
    float4 f2 = __ldg(fr + 2), f3 = __ldg(fr + 3);
    float4 f4 = __ldg(fr + 4), f5 = __ldg(fr + 5);
    float4 f6 = __ldg(fr + 6), f7 = __ldg(fr + 7);
    float fv[32] = {
        f0.x, f0.y, f0.z, f0.w, f1.x, f1.y, f1.z, f1.w,
        f2.x, f2.y, f2.z, f2.w, f3.x, f3.y, f3.z, f3.w,
        f4.x, f4.y, f4.z, f4.w, f5.x, f5.y, f5.z, f5.w,
        f6.x, f6.y, f6.z, f6.w, f7.x, f7.y, f7.z, f7.w };
#pragma unroll
    for (int cin = 0; cin < 32; cin++) {
        unsigned long long bc;
        PACK2(bc, fv[cin]);
        const ulonglong2* wv = (const ulonglong2*)(wbase + cin * 16);
#pragma unroll
        for (int h = 0; h < 8; h++) {
            ulonglong2 wp = wv[h];
            FMA2(acc[2 * h],     bc, wp.x, acc[2 * h]);
            FMA2(acc[2 * h + 1], bc, wp.y, acc[2 * h + 1]);
        }
    }
}

// ============================================================
// 1. prep: reset counters + BN sums, scatter lookup
// ============================================================
__global__ void prep_kernel(const int4* __restrict__ coords) {
    int i = blockIdx.x * blockDim.x + threadIdx.x;
    if (i < 8) d_cnt[i] = 0;
    if (i >= 8 && i < 72) d_sums[i - 8] = 0.0f;
    if (i < NPTS) {
        int4 c = coords[i];
        d_lookup[((c.x * SX + c.y) * SY + c.z) * SZ + c.w] = i + 1;
    }
}

// ============================================================
// 2. probe: per-k pair lists + flags + zero flagged out rows
// ============================================================
__global__ __launch_bounds__(256) void probe_kernel(const int4* __restrict__ coords,
                                                    float* __restrict__ out) {
    __shared__ int s_wcnt[8][8];
    __shared__ int s_wbase[8][8];
    int tid  = threadIdx.x;
    int lane = tid & 31;
    int warp = tid >> 5;
    int pt = blockIdx.x * 256 + tid;
    bool act = pt < NPTS;

    int4 cc = act ? coords[pt] : make_int4(0, 1, 0, 1);
    int base = ((cc.x * SX + cc.y) * SY + cc.z) * SZ + cc.w;

    unsigned mask = 0;
    int nb[8];
#pragma unroll
    for (int k = 0; k < 9; k++) {
        if (k == 4) continue;
        int d0 = k / 3 - 1, d2 = k % 3 - 1;
        int n0 = cc.y + d0, n2 = cc.w + d2;
        bool valid = act && (n0 >= 0) && (n0 < SX) && (n2 >= 0) && (n2 < SZ);
        int idx = valid ? (base + d0 * (SY * SZ) + d2) : 0;
        int j = valid ? __ldg(&d_lookup[idx]) : 0;
        int ki = (k < 4) ? k : k - 1;
        nb[ki] = j - 1;
        if (j > 0) mask |= (1u << ki);
    }

    if (act) d_flag[pt] = (unsigned char)(mask ? 1 : 0);

    // cooperative zero of flagged rows (these receive red.adds)
    {
        unsigned fb = __ballot_sync(0xffffffffu, act && mask);
        int wbase_pt = blockIdx.x * 256 + warp * 32;
        while (fb) {
            int p = __ffs(fb) - 1;
            fb &= fb - 1;
            out[(long long)(wbase_pt + p) * CCH + lane] = 0.0f;
        }
    }

    unsigned bal[8];
#pragma unroll
    for (int ki = 0; ki < 8; ki++)
        bal[ki] = __ballot_sync(0xffffffffu, (mask >> ki) & 1u);
    if (lane == 0) {
#pragma unroll
        for (int ki = 0; ki < 8; ki++)
            s_wcnt[ki][warp] = __popc(bal[ki]);
    }
    __syncthreads();
    if (tid < 8) {
        int run = 0;
#pragma unroll
        for (int w = 0; w < 8; w++) {
            int c = s_wcnt[tid][w];
            s_wbase[tid][w] = run;
            run += c;
        }
        int g = atomicAdd(&d_cnt[tid], run);
#pragma unroll
        for (int w = 0; w < 8; w++)
            s_wbase[tid][w] += g;
    }
    __syncthreads();
#pragma unroll
    for (int ki = 0; ki < 8; ki++) {
        if ((mask >> ki) & 1u) {
            int rank = __popc(bal[ki] & ((1u << lane) - 1u));
            d_pairs[ki][s_wbase[ki][warp] + rank] = make_int2(pt, nb[ki]);
        }
    }
}

// ============================================================
// 3. neighbor conv: grid.y = ki, one thread per pair, uniform-k
// ============================================================
__global__ __launch_bounds__(256) void neighbor_kernel(
    const float* __restrict__ feat,
    const float* __restrict__ weight,
    float*       __restrict__ out)
{
    int ki = blockIdx.y;
    int k  = (ki < 4) ? ki : ki + 1;
    __shared__ unsigned long long w2[512];
    {
        const unsigned long long* ws =
            (const unsigned long long*)(weight + k * 1024);
        for (int i = threadIdx.x; i < 512; i += 256)
            w2[i] = ws[i];
    }
    __syncthreads();

    int n = d_cnt[ki];
    for (int p = blockIdx.x * 256 + threadIdx.x; p < n; p += gridDim.x * 256) {
        int2 pr = d_pairs[ki][p];
        unsigned long long acc[16];
#pragma unroll
        for (int q = 0; q < 16; q++) acc[q] = 0ull;
        gemv_accum(feat + (long long)pr.y * CCH, w2, acc);

        float* orow = out + (long long)pr.x * CCH;
#pragma unroll
        for (int h = 0; h < 8; h++) {
            unsigned int u0, u1, u2, u3;
            UNPACK2(u0, u1, acc[2 * h]);
            UNPACK2(u2, u3, acc[2 * h + 1]);
            asm volatile("red.global.add.v4.f32 [%0], {%1, %2, %3, %4};"
                         :: "l"(orow + 4 * h),
                            "f"(__uint_as_float(u0)), "f"(__uint_as_float(u1)),
                            "f"(__uint_as_float(u2)), "f"(__uint_as_float(u3))
                         : "memory");
        }
    }
}

// ============================================================
// 4. self conv via mma.sync bf16 3-product split (M=256, N=32)
//    2 M-tiles per warp sharing B fragments; warp-local epilogue
//    (R13 structure; launch_bounds(256,4) -> 4 CTAs/SM)
// ============================================================
#define ASTR 72       // bf16/row: 144 B = 9 x 16B (odd) -> ldmatrix conflict-free
#define BSTR 104      // bf16/row: 208 B = 13 x 16B (odd)
#define BPTS 256

__global__ __launch_bounds__(256, 4) void selfleaky_mma_kernel(
    const float* __restrict__ feat,
    const float* __restrict__ weight,
    float*       __restrict__ out)
{
    __shared__ __align__(16) __nv_bfloat16 s_A[BPTS * ASTR];  // 36864 B
    __shared__ __align__(16) __nv_bfloat16 s_B[32 * BSTR];    //  6656 B
    __shared__ unsigned char s_flag[BPTS];
    __shared__ float s_sum[32], s_sq[32];
    float* s_out = (float*)s_A;   // overlay: 256*36*4 = 36864 B exact

    int tid  = threadIdx.x;
    int wrp  = tid >> 5;
    int lane = tid & 31;
    int blk0 = blockIdx.x * BPTS;
    int gbase = blk0 * 8;                 // float4 index base
    const int gmax = NPTS * 8;

    if (tid < 32) { s_sum[tid] = 0.0f; s_sq[tid] = 0.0f; }
    s_flag[tid] = (blk0 + tid < NPTS) ? d_flag[blk0 + tid] : 0;

    // ---- stage A: coalesced LDG.128 (evict-first), bf16 split ----
    {
        const float4* f4 = (const float4*)feat;
#pragma unroll
        for (int i = 0; i < 8; i++) {
            int idx = i * 256 + tid;               // 0..2047
            int g = gbase + idx;
            float4 v = (g < gmax) ? ldcs4(f4 + g)
                                  : make_float4(0.f, 0.f, 0.f, 0.f);
            int r  = idx >> 3;
            int c4 = (idx & 7) << 2;               // bf16 col: 0,4,..28
            __nv_bfloat162 h01 = __floats2bfloat162_rn(v.x, v.y);
            __nv_bfloat162 h23 = __floats2bfloat162_rn(v.z, v.w);
            __nv_bfloat162 l01 = __floats2bfloat162_rn(
                v.x - __bfloat162float(h01.x), v.y - __bfloat162float(h01.y));
            __nv_bfloat162 l23 = __floats2bfloat162_rn(
                v.z - __bfloat162float(h23.x), v.w - __bfloat162float(h23.y));
            uint2 hh = make_uint2(*(uint32_t*)&h01, *(uint32_t*)&h23);
            uint2 ll = make_uint2(*(uint32_t*)&l01, *(uint32_t*)&l23);
            *(uint2*)&s_A[r * ASTR + c4]      = hh;   // xh cols 0..31
            *(uint2*)&s_A[r * ASTR + 32 + c4] = ll;   // xl cols 32..63
        }
    }

    // ---- stage B: weights k=4, transpose to [cout][wh|wh|wl] ----
    {
        float4 wv = __ldg((const float4*)(weight + 4 * 1024) + tid);
        int el  = tid * 4;
        int cin = el >> 5;
        int n0  = el & 31;
        float wf[4] = { wv.x, wv.y, wv.z, wv.w };
#pragma unroll
        for (int j = 0; j < 4; j++) {
            int n = n0 + j;
            __nv_bfloat16 wh = __float2bfloat16(wf[j]);
            __nv_bfloat16 wl = __float2bfloat16(wf[j] - __bfloat162float(wh));
            s_B[n * BSTR + cin]      = wh;
            s_B[n * BSTR + 32 + cin] = wh;
            s_B[n * BSTR + 64 + cin] = wl;
        }
    }
    __syncthreads();

    // ---- warp MMA: 2 tiles, rows [16w,16w+16) and +128; shared B frags ----
    float c00[4] = {0,0,0,0}, c01[4] = {0,0,0,0},
          c02[4] = {0,0,0,0}, c03[4] = {0,0,0,0};
    float c10[4] = {0,0,0,0}, c11[4] = {0,0,0,0},
          c12[4] = {0,0,0,0}, c13[4] = {0,0,0,0};
    {
        uint32_t a_base0 = smem_u32(s_A) + ((wrp * 16 + (lane & 15)) * ASTR
                         + (lane >> 4) * 8) * 2;
        uint32_t a_base1 = a_base0 + 128 * ASTR * 2;
        uint32_t b_base0 = smem_u32(s_B) + ((lane & 15) * BSTR
                         + (lane >> 4) * 8) * 2;
        uint32_t b_base1 = b_base0 + 16 * BSTR * 2;
#pragma unroll
        for (int s = 0; s < 6; s++) {
            uint32_t a_koff = (s < 4 ? s : s - 4) * 32;   // bytes (16 bf16)
            uint32_t b_koff = s * 32;
            uint32_t p0, p1, p2, p3, q0, q1, q2, q3;
            LDSM_X4(p0, p1, p2, p3, b_base0 + b_koff);
            LDSM_X4(q0, q1, q2, q3, b_base1 + b_koff);
            uint32_t a0, a1, a2, a3;
            LDSM_X4(a0, a1, a2, a3, a_base0 + a_koff);
            MMA_BF16(c00, a0, a1, a2, a3, p0, p2);
            MMA_BF16(c01, a0, a1, a2, a3, p1, p3);
            MMA_BF16(c02, a0, a1, a2, a3, q0, q2);
            MMA_BF16(c03, a0, a1, a2, a3, q1, q3);
            uint32_t e0, e1, e2, e3;
            LDSM_X4(e0, e1, e2, e3, a_base1 + a_koff);
            MMA_BF16(c10, e0, e1, e2, e3, p0, p2);
            MMA_BF16(c11, e0, e1, e2, e3, p1, p3);
            MMA_BF16(c12, e0, e1, e2, e3, q0, q2);
            MMA_BF16(c13, e0, e1, e2, e3, q1, q3);
        }
    }

    // ---- warp-local epilogue: acc -> s_out (own rows only; no barrier) ----
    {
        int g  = lane >> 2;
        int tg = lane & 3;
        int r0 = wrp * 16 + g;
        float* ro = &s_out[r0 * 36 + 2 * tg];
        float* r8 = &s_out[(r0 + 8) * 36 + 2 * tg];
        *(float2*)(ro + 0)  = make_float2(c00[0], c00[1]);
        *(float2*)(r8 + 0)  = make_float2(c00[2], c00[3]);
        *(float2*)(ro + 8)  = make_float2(c01[0], c01[1]);
        *(float2*)(r8 + 8)  = make_float2(c01[2], c01[3]);
        *(float2*)(ro + 16) = make_float2(c02[0], c02[1]);
        *(float2*)(r8 + 16) = make_float2(c02[2], c02[3]);
        *(float2*)(ro + 24) = make_float2(c03[0], c03[1]);
        *(float2*)(r8 + 24) = make_float2(c03[2], c03[3]);
        float* so = ro + 128 * 36;
        float* s8 = r8 + 128 * 36;
        *(float2*)(so + 0)  = make_float2(c10[0], c10[1]);
        *(float2*)(s8 + 0)  = make_float2(c10[2], c10[3]);
        *(float2*)(so + 8)  = make_float2(c11[0], c11[1]);
        *(float2*)(s8 + 8)  = make_float2(c11[2], c11[3]);
        *(float2*)(so + 16) = make_float2(c12[0], c12[1]);
        *(float2*)(s8 + 16) = make_float2(c12[2], c12[3]);
        *(float2*)(so + 24) = make_float2(c13[0], c13[1]);
        *(float2*)(s8 + 24) = make_float2(c13[2], c13[3]);
    }
    __syncthreads();

    // ---- fused writeback: +partials, leaky, store, BN accumulate ----
    float bs0 = 0.f, bs1 = 0.f, bs2 = 0.f, bs3 = 0.f;
    float bq0 = 0.f, bq1 = 0.f, bq2 = 0.f, bq3 = 0.f;
    {
        float4* o4 = (float4*)out;
#pragma unroll
        for (int i = 0; i < 8; i++) {
            int idx = i * 256 + tid;
            int g = gbase + idx;
            if (g < gmax) {
                int r = idx >> 3;
                int c = (idx & 7) << 2;
                float4 v = *(const float4*)&s_out[r * 36 + c];
                if (s_flag[r]) {
                    float4 p = __ldg(o4 + g);
                    v.x += p.x; v.y += p.y; v.z += p.z; v.w += p.w;
                }
                v.x = fmaxf(v.x, 0.01f * v.x);
                v.y = fmaxf(v.y, 0.01f * v.y);
                v.z = fmaxf(v.z, 0.01f * v.z);
                v.w = fmaxf(v.w, 0.01f * v.w);
                o4[g] = v;
                bs0 += v.x; bq0 = fmaf(v.x, v.x, bq0);
                bs1 += v.y; bq1 = fmaf(v.y, v.y, bq1);
                bs2 += v.z; bq2 = fmaf(v.z, v.z, bq2);
                bs3 += v.w; bq3 = fmaf(v.w, v.w, bq3);
            }
        }
    }
    {
        int cq = (tid & 7) * 4;
        atomicAdd(&s_sum[cq + 0], bs0);
        atomicAdd(&s_sum[cq + 1], bs1);
        atomicAdd(&s_sum[cq + 2], bs2);
        atomicAdd(&s_sum[cq + 3], bs3);
        atomicAdd(&s_sq[cq + 0], bq0);
        atomicAdd(&s_sq[cq + 1], bq1);
        atomicAdd(&s_sq[cq + 2], bq2);
        atomicAdd(&s_sq[cq + 3], bq3);
    }
    __syncthreads();
    if (tid < 32) {
        atomicAdd(&d_sums[tid],      s_sum[tid]);
        atomicAdd(&d_sums[32 + tid], s_sq[tid]);
    }
}

// ============================================================
// 5. normalize in place: 8 independent float4/thread, evict-first reads
// ============================================================
__global__ __launch_bounds__(256) void norm_kernel(float4* __restrict__ y,
                                                   const float* __restrict__ gamma,
                                                   const float* __restrict__ beta) {
    __shared__ float s_sc[32], s_sh[32];
    if (threadIdx.x < 32) {
        int c = threadIdx.x;
        const float invN = 1.0f / (float)NPTS;
        float sum = __ldg(&d_sums[c]);
        float sq  = __ldg(&d_sums[32 + c]);
        float mean = sum * invN;
        float var  = sq * invN - mean * mean;
        float sc   = __ldg(&gamma[c]) * rsqrtf(var + EPSV);
        s_sc[c] = sc;
        s_sh[c] = __ldg(&beta[c]) - mean * sc;
    }
    __syncthreads();
    int base = blockIdx.x * 2048;
    const int total = NPTS * 8;
    // batch 8 independent loads first (MLP=8), then transform+store
    float4 v[8];
    int t[8];
#pragma unroll
    for (int i = 0; i < 8; i++) {
        t[i] = base + i * 256 + threadIdx.x;
        v[i] = (t[i] < total) ? ldcs4(y + t[i])
                              : make_float4(0.f, 0.f, 0.f, 0.f);
    }
#pragma unroll
    for (int i = 0; i < 8; i++) {
        if (t[i] < total) {
            int c0 = (t[i] & 7) * 4;
            float4 w = v[i];
            w.x = fmaf(w.x, s_sc[c0 + 0], s_sh[c0 + 0]);
            w.y = fmaf(w.y, s_sc[c0 + 1], s_sh[c0 + 1]);
            w.z = fmaf(w.z, s_sc[c0 + 2], s_sh[c0 + 2]);
            w.w = fmaf(w.w, s_sc[c0 + 3], s_sh[c0 + 3]);
            y[t[i]] = w;
        }
    }
}

// ============================================================
extern "C" void kernel_launch(void* const* d_in, const int* in_sizes, int n_in,
                              void* d_out, int out_size) {
    const float* feat   = (const float*)d_in[0];
    const int4*  coords = (const int4*)d_in[1];
    const float* weight = (const float*)d_in[2];
    const float* gamma  = (const float*)d_in[3];
    const float* beta   = (const float*)d_in[4];
    float* out = (float*)d_out;

    prep_kernel<<<(NPTS + 255) / 256, 256>>>(coords);
    probe_kernel<<<(NPTS + 255) / 256, 256>>>(coords, out);
    neighbor_kernel<<<dim3(64, 8), 256>>>(feat, weight, out);
    selfleaky_mma_kernel<<<(NPTS + BPTS - 1) / BPTS, 256>>>(feat, weight, out);
    norm_kernel<<<(NPTS * 8 + 2047) / 2048, 256>>>((float4*)out, gamma, beta);
}